// round 6
// baseline (speedup 1.0000x reference)
#include <cuda_runtime.h>
#include <cstddef>

#define Bk 32
#define Nk 1535
#define NN 1536
#define Hk 64

// Scratch (no allocations allowed -> __device__ globals)
__device__ float g_h[(size_t)Bk * Hk * NN];   // [b][h][j]  ~12.6 MB
__device__ float g_sk[Bk * NN];
__device__ float g_m[Bk * Hk];

// ---- packed f32x2 helpers (sm_10x FFMA2; per-lane rounding == scalar FMA) ----
__device__ __forceinline__ unsigned long long fma2(unsigned long long a,
                                                   unsigned long long b,
                                                   unsigned long long c) {
    unsigned long long d;
    asm("fma.rn.f32x2 %0, %1, %2, %3;" : "=l"(d) : "l"(a), "l"(b), "l"(c));
    return d;
}
__device__ __forceinline__ unsigned long long pack2(float lo, float hi) {
    unsigned long long d;
    asm("mov.b64 %0, {%1, %2};" : "=l"(d) : "f"(lo), "f"(hi));
    return d;
}
__device__ __forceinline__ float2 unpack2(unsigned long long v) {
    float2 r;
    asm("mov.b64 {%0, %1}, %2;" : "=f"(r.x), "=f"(r.y) : "l"(v));
    return r;
}

// ---------------------------------------------------------------------------
// K1: encoder MLP per (b, node j) + sk dot.  grid (12, 32), 128 thr.
//     FFMA2-packed; layer-1 output stays PACKED (h1p) and layer-2 outputs are
//     computed in two 16-accumulator halves -> no spills at (128,2).
//     kvec = WK^T wQKk recomputed per block (trivial vs body); the additive
//     softmax constant bK.wQKk cancels (shift invariance) and is dropped.
//     Writes h to [b][h][j] layout (coalesced over j).
// ---------------------------------------------------------------------------
__global__ __launch_bounds__(128, 2) void k1_encode(
    const float* __restrict__ xx,   // [B,N,8]
    const float* __restrict__ yy,   // [B,N]
    const float* __restrict__ oxx,  // [B,1,8]
    const float* __restrict__ W1, const float* __restrict__ b1,
    const float* __restrict__ W2, const float* __restrict__ b2,
    const float* __restrict__ Wenc, const float* __restrict__ benc,
    const float* __restrict__ WK, const float* __restrict__ wQKk) {
    __shared__ __align__(16) float W1T[9 * Hk];    // [i][o]
    __shared__ __align__(16) float W2T[Hk * Hk];   // [i][o] (transposed)
    __shared__ __align__(16) float WencT[8 * Hk];  // [i][o]
    __shared__ __align__(16) float b1s[Hk];
    __shared__ __align__(16) float b2s[Hk];
    __shared__ float kvs[Hk], bencs[Hk], wqks[Hk];

    const int tid = threadIdx.x;
    const int b = blockIdx.y;

    for (int t = tid; t < 9 * Hk; t += 128) { int o = t / 9, i = t % 9; W1T[i * Hk + o] = W1[t]; }
    for (int t = tid; t < 8 * Hk; t += 128) { int o = t / 8, i = t % 8; WencT[i * Hk + o] = Wenc[t]; }
    for (int t = tid; t < Hk * Hk; t += 128) { int o = t >> 6, i = t & 63; W2T[i * Hk + o] = W2[t]; }
    if (tid < Hk) { b1s[tid] = b1[tid]; b2s[tid] = b2[tid]; bencs[tid] = benc[tid]; wqks[tid] = wQKk[tid]; }
    __syncthreads();

    // kvec[o] = sum_hp WK[hp][o] * wQKk[hp]  (coalesced over lanes)
    if (tid < Hk) {
        float acc = 0.f;
        #pragma unroll 8
        for (int hp = 0; hp < Hk; hp++) acc += WK[hp * Hk + tid] * wqks[hp];
        kvs[tid] = acc;
    }
    __syncthreads();

    const int j = blockIdx.x * 128 + tid;

    if (j < Nk) {
        float x[9];
        const float4* xp = (const float4*)(xx + ((size_t)b * Nk + j) * 8);
        float4 xa = xp[0], xb4 = xp[1];
        x[0] = xa.x; x[1] = xa.y; x[2] = xa.z; x[3] = xa.w;
        x[4] = xb4.x; x[5] = xb4.y; x[6] = xb4.z; x[7] = xb4.w;
        x[8] = yy[b * Nk + j];

        // ---- layer 1 (packed o-pairs; stays packed) ----
        unsigned long long h1p[32];
        {
            const ulonglong2* bp = (const ulonglong2*)b1s;
            #pragma unroll
            for (int q = 0; q < 16; q++) { ulonglong2 v = bp[q]; h1p[2 * q] = v.x; h1p[2 * q + 1] = v.y; }
        }
        #pragma unroll
        for (int i = 0; i < 9; i++) {
            const unsigned long long xbp = pack2(x[i], x[i]);
            const ulonglong2* wr = (const ulonglong2*)(W1T + i * Hk);
            #pragma unroll
            for (int q = 0; q < 16; q++) {
                ulonglong2 wv = wr[q];
                h1p[2 * q]     = fma2(wv.x, xbp, h1p[2 * q]);
                h1p[2 * q + 1] = fma2(wv.y, xbp, h1p[2 * q + 1]);
            }
        }

        // ---- layer 2 in two output halves (16 ull accumulators each) ----
        float skacc = 0.f;
        float* hout = g_h + (size_t)b * Hk * NN + j;
        #pragma unroll
        for (int half = 0; half < 2; half++) {
            unsigned long long acc[16];
            {
                const ulonglong2* bp = (const ulonglong2*)(b2s + half * 32);
                #pragma unroll
                for (int q = 0; q < 8; q++) { ulonglong2 v = bp[q]; acc[2 * q] = v.x; acc[2 * q + 1] = v.y; }
            }
            #pragma unroll 2
            for (int ip = 0; ip < 32; ip++) {
                float2 hv = unpack2(h1p[ip]);
                const float e0 = fmaxf(hv.x, 0.f), e1 = fmaxf(hv.y, 0.f);
                const unsigned long long hb0 = pack2(e0, e0);
                const unsigned long long hb1 = pack2(e1, e1);
                const ulonglong2* wr0 = (const ulonglong2*)(W2T + (2 * ip) * Hk + half * 32);
                const ulonglong2* wr1 = (const ulonglong2*)(W2T + (2 * ip + 1) * Hk + half * 32);
                #pragma unroll
                for (int q = 0; q < 8; q++) {
                    ulonglong2 wv0 = wr0[q];
                    acc[2 * q]     = fma2(wv0.x, hb0, acc[2 * q]);
                    acc[2 * q + 1] = fma2(wv0.y, hb0, acc[2 * q + 1]);
                }
                #pragma unroll
                for (int q = 0; q < 8; q++) {
                    ulonglong2 wv1 = wr1[q];
                    acc[2 * q]     = fma2(wv1.x, hb1, acc[2 * q]);
                    acc[2 * q + 1] = fma2(wv1.y, hb1, acc[2 * q + 1]);
                }
            }
            #pragma unroll
            for (int q = 0; q < 16; q++) {
                float2 v = unpack2(acc[q]);
                const int o = half * 32 + 2 * q;
                float a0 = fmaxf(v.x, 0.f), a1 = fmaxf(v.y, 0.f);
                hout[(size_t)o * NN] = a0;
                hout[(size_t)(o + 1) * NN] = a1;
                skacc += a0 * kvs[o] + a1 * kvs[o + 1];
            }
        }
        g_sk[b * NN + j] = skacc;
    } else if (j == Nk) {
        // output node: relu(Wenc @ output_xx[b,0,:] + benc)
        float x[8];
        const float* xp = oxx + b * 8;
        #pragma unroll
        for (int i = 0; i < 8; i++) x[i] = xp[i];
        float skacc = 0.f;
        float* hout = g_h + (size_t)b * Hk * NN + j;
        #pragma unroll
        for (int o = 0; o < Hk; o++) {
            float acc = bencs[o];
            #pragma unroll
            for (int i = 0; i < 8; i++) acc += WencT[i * Hk + o] * x[i];
            acc = fmaxf(acc, 0.f);
            hout[(size_t)o * NN] = acc;
            skacc += acc * kvs[o];
        }
        g_sk[b * NN + j] = skacc;
    }
}

// ---------------------------------------------------------------------------
// K23: fused softmax + weighted reduce.  grid (8, 32) = (o-group, b), 256 thr.
// ---------------------------------------------------------------------------
__global__ __launch_bounds__(256) void k23_softmax_reduce() {
    const int og = blockIdx.x, b = blockIdx.y;
    const int tid = threadIdx.x;
    const int lane = tid & 31, warp = tid >> 5;
    __shared__ __align__(16) float wsh[NN];
    __shared__ float red[8];

    // softmax over sk[b][:]
    float vals[6];
    float mx = -1e30f;
    #pragma unroll
    for (int t = 0; t < 6; t++) {
        vals[t] = g_sk[b * NN + t * 256 + tid];
        mx = fmaxf(mx, vals[t]);
    }
    #pragma unroll
    for (int s = 16; s > 0; s >>= 1) mx = fmaxf(mx, __shfl_xor_sync(0xffffffffu, mx, s));
    if (lane == 0) red[warp] = mx;
    __syncthreads();
    if (tid == 0) {
        float m = red[0];
        #pragma unroll
        for (int w = 1; w < 8; w++) m = fmaxf(m, red[w]);
        red[0] = m;
    }
    __syncthreads();
    mx = red[0];
    __syncthreads();

    float sum = 0.f;
    #pragma unroll
    for (int t = 0; t < 6; t++) { vals[t] = __expf(vals[t] - mx); sum += vals[t]; }
    #pragma unroll
    for (int s = 16; s > 0; s >>= 1) sum += __shfl_xor_sync(0xffffffffu, sum, s);
    if (lane == 0) red[warp] = sum;
    __syncthreads();
    if (tid == 0) {
        float s = 0.f;
        #pragma unroll
        for (int w = 0; w < 8; w++) s += red[w];
        red[0] = 1.f / s;
    }
    __syncthreads();
    const float inv = red[0];
    #pragma unroll
    for (int t = 0; t < 6; t++) wsh[t * 256 + tid] = vals[t] * inv;
    __syncthreads();

    // weighted reduce: m[b][o] = sum_j w[j] * h[b][o][j], 8 rows per block
    const int ol = tid >> 5;             // 0..7
    const int o = og * 8 + ol;
    const float4* hp = (const float4*)(g_h + ((size_t)b * Hk + o) * NN);
    const float4* wp = (const float4*)wsh;
    float acc = 0.f;
    #pragma unroll
    for (int k = 0; k < 12; k++) {
        float4 hv = hp[lane + 32 * k];
        float4 wv = wp[lane + 32 * k];
        acc += hv.x * wv.x + hv.y * wv.y + hv.z * wv.z + hv.w * wv.w;
    }
    #pragma unroll
    for (int s = 16; s > 0; s >>= 1) acc += __shfl_down_sync(0xffffffffu, acc, s);
    if (lane == 0) g_m[b * Hk + o] = acc;
}

// ---------------------------------------------------------------------------
// K4: collapsed rounds, warp-local BN.  1 block, 512 thr (16 warps).
//     Prologue computes Wc = WA@WV packed as Wq[op][h] and bc = WA@bV + bA
//     in-block (removes the separate k0 launch).
//     Mainloop: lane = batch b, warp w owns h = 4w..4w+3; node state packed
//     o-pairs nsP[op][b], double-buffered; BN stats via warp shuffles;
//     ONE __syncthreads per round.
// ---------------------------------------------------------------------------
__global__ __launch_bounds__(512) void k4_tail(
    const float* __restrict__ WV, const float* __restrict__ bV,
    const float* __restrict__ WA, const float* __restrict__ bA,
    const float* __restrict__ gamma, const float* __restrict__ beta,
    const float* __restrict__ Wmu, const float* __restrict__ bmu,
    const float* __restrict__ Wsig, const float* __restrict__ bsig,
    float* __restrict__ out) {
    __shared__ __align__(16) unsigned long long Wq[32 * 64];     // [op][h] 16KB
    __shared__ __align__(16) unsigned long long WVp[64 * 32];    // [k][op] 16KB
    __shared__ __align__(16) float WAs[Hk * Hk];                 // 16KB
    __shared__ __align__(16) unsigned long long nsP[2][32 * 32]; // [op][b] 16KB
    __shared__ float bcs[Hk], gam[Hk], bet[Hk], wmus[Hk], wsigs[Hk], bVs[Hk];
    __shared__ float hpm[16 * 32], hps[16 * 32];

    const int tid = threadIdx.x;
    const int lane = tid & 31;          // = batch b
    const int w = tid >> 5;             // warp 0..15, h = 4w..4w+3
    const int h0 = 4 * w;

    // ---- Prologue stage ----
    for (int t = tid; t < Hk * Hk; t += 512) WAs[t] = WA[t];
    for (int t = tid; t < Hk * 32; t += 512) {
        const int k = t >> 5, op = t & 31;
        const float2 v = *(const float2*)(WV + k * Hk + 2 * op);
        WVp[k * 32 + op] = pack2(v.x, v.y);
    }
    for (int t = tid; t < 1024; t += 512) {
        const int op = t >> 5, b = t & 31;
        nsP[0][op * 32 + b] = pack2(g_m[b * Hk + 2 * op], g_m[b * Hk + 2 * op + 1]);
    }
    if (tid < Hk) {
        gam[tid] = gamma[tid]; bet[tid] = beta[tid];
        wmus[tid] = Wmu[tid]; wsigs[tid] = Wsig[tid]; bVs[tid] = bV[tid];
    }
    __syncthreads();

    // ---- Wc = WA@WV packed: Wq[op][h] = (Wc[h][2op], Wc[h][2op+1]) ----
    for (int t = tid; t < 2048; t += 512) {
        const int op = t & 31, h = t >> 5;
        unsigned long long acc = 0ull;
        #pragma unroll 8
        for (int k = 0; k < Hk; k++) {
            const float a = WAs[h * Hk + k];
            acc = fma2(pack2(a, a), WVp[k * 32 + op], acc);
        }
        Wq[op * 64 + h] = acc;
    }
    if (tid < Hk) {
        float acc = bA[tid];
        #pragma unroll 8
        for (int k = 0; k < Hk; k++) acc += WAs[tid * Hk + k] * bVs[k];
        bcs[tid] = acc;
    }
    __syncthreads();

    // ---- Mainloop ----
    float r0 = 0.f, r1 = 0.f, r2 = 0.f, r3 = 0.f;
    int p = 0;

    #pragma unroll
    for (int r = 0; r < 4; r++) {
        unsigned long long a0 = 0ull, a1 = 0ull, a2 = 0ull, a3 = 0ull;
        const unsigned long long* ns = nsP[p];
        #pragma unroll
        for (int op = 0; op < 32; op++) {
            const unsigned long long nb = ns[op * 32 + lane];
            ulonglong2 wv0 = *(const ulonglong2*)(Wq + op * 64 + h0);
            ulonglong2 wv1 = *(const ulonglong2*)(Wq + op * 64 + h0 + 2);
            a0 = fma2(nb, wv0.x, a0); a1 = fma2(nb, wv0.y, a1);
            a2 = fma2(nb, wv1.x, a2); a3 = fma2(nb, wv1.y, a3);
        }
        float2 v0 = unpack2(a0), v1 = unpack2(a1), v2 = unpack2(a2), v3 = unpack2(a3);
        float z0 = v0.x + v0.y + bcs[h0];
        float z1 = v1.x + v1.y + bcs[h0 + 1];
        float z2 = v2.x + v2.y + bcs[h0 + 2];
        float z3 = v3.x + v3.y + bcs[h0 + 3];

        // warp-local BN over lanes (= all 32 batches)
        float s0 = z0, q0 = z0 * z0, s1 = z1, q1 = z1 * z1;
        float s2 = z2, q2 = z2 * z2, s3 = z3, q3 = z3 * z3;
        #pragma unroll
        for (int d = 16; d > 0; d >>= 1) {
            s0 += __shfl_xor_sync(0xffffffffu, s0, d);
            q0 += __shfl_xor_sync(0xffffffffu, q0, d);
            s1 += __shfl_xor_sync(0xffffffffu, s1, d);
            q1 += __shfl_xor_sync(0xffffffffu, q1, d);
            s2 += __shfl_xor_sync(0xffffffffu, s2, d);
            q2 += __shfl_xor_sync(0xffffffffu, q2, d);
            s3 += __shfl_xor_sync(0xffffffffu, s3, d);
            q3 += __shfl_xor_sync(0xffffffffu, q3, d);
        }
        const float mu0 = s0 * (1.f / Bk), mu1 = s1 * (1.f / Bk);
        const float mu2 = s2 * (1.f / Bk), mu3 = s3 * (1.f / Bk);
        const float sc0 = gam[h0]     * rsqrtf(q0 * (1.f / Bk) - mu0 * mu0 + 1e-5f);
        const float sc1 = gam[h0 + 1] * rsqrtf(q1 * (1.f / Bk) - mu1 * mu1 + 1e-5f);
        const float sc2 = gam[h0 + 2] * rsqrtf(q2 * (1.f / Bk) - mu2 * mu2 + 1e-5f);
        const float sc3 = gam[h0 + 3] * rsqrtf(q3 * (1.f / Bk) - mu3 * mu3 + 1e-5f);
        r0 = fmaxf((z0 - mu0) * sc0 + bet[h0], 0.f);
        r1 = fmaxf((z1 - mu1) * sc1 + bet[h0 + 1], 0.f);
        r2 = fmaxf((z2 - mu2) * sc2 + bet[h0 + 2], 0.f);
        r3 = fmaxf((z3 - mu3) * sc3 + bet[h0 + 3], 0.f);

        // write next-round state (h-pairs -> op rows 2w, 2w+1)
        nsP[1 - p][(2 * w) * 32 + lane]     = pack2(r0, r1);
        nsP[1 - p][(2 * w + 1) * 32 + lane] = pack2(r2, r3);
        __syncthreads();
        p ^= 1;
    }

    // Heads: agg = final node vector (all nodes identical).
    hpm[w * 32 + lane] = r0 * wmus[h0] + r1 * wmus[h0 + 1]
                       + r2 * wmus[h0 + 2] + r3 * wmus[h0 + 3];
    hps[w * 32 + lane] = r0 * wsigs[h0] + r1 * wsigs[h0 + 1]
                       + r2 * wsigs[h0 + 2] + r3 * wsigs[h0 + 3];
    __syncthreads();
    if (tid < Bk) {
        float m = bmu[0], s = bsig[0];
        #pragma unroll
        for (int ww = 0; ww < 16; ww++) {
            m += hpm[ww * 32 + tid];
            s += hps[ww * 32 + tid];
        }
        out[tid] = m;
        out[Bk + tid] = s * s + 0.01f;
    }
}

// ---------------------------------------------------------------------------
extern "C" void kernel_launch(void* const* d_in, const int* in_sizes, int n_in,
                              void* d_out, int out_size) {
    const float* xx   = (const float*)d_in[0];   // input_xx  [32,1535,8]
    const float* yy   = (const float*)d_in[1];   // input_yy  [32,1535]
    const float* oxx  = (const float*)d_in[2];   // output_xx [32,1,8]
    const float* W1   = (const float*)d_in[3];
    const float* b1   = (const float*)d_in[4];
    const float* W2   = (const float*)d_in[5];
    const float* b2   = (const float*)d_in[6];
    const float* Wenc = (const float*)d_in[7];
    const float* benc = (const float*)d_in[8];
    // d_in[9], d_in[10] = WQ, bQ  (cancel in softmax -> unused)
    const float* WK   = (const float*)d_in[11];
    // d_in[12] = bK (its softmax contribution is j-constant -> cancels)
    const float* WV   = (const float*)d_in[13];
    const float* bV   = (const float*)d_in[14];
    // d_in[15] = wQKq (cancels), d_in[17] = bQK (cancels)
    const float* wQKk = (const float*)d_in[16];
    const float* WA   = (const float*)d_in[18];
    const float* bA   = (const float*)d_in[19];
    const float* gamma= (const float*)d_in[20];
    const float* beta = (const float*)d_in[21];
    const float* Wmu  = (const float*)d_in[22];
    const float* bmu  = (const float*)d_in[23];
    const float* Wsig = (const float*)d_in[24];
    const float* bsig = (const float*)d_in[25];
    float* out = (float*)d_out;

    dim3 g1(12, 32);
    k1_encode<<<g1, 128>>>(xx, yy, oxx, W1, b1, W2, b2, Wenc, benc, WK, wQKk);
    dim3 g23(8, 32);
    k23_softmax_reduce<<<g23, 256>>>();
    k4_tail<<<1, 512>>>(WV, bV, WA, bA, gamma, beta, Wmu, bmu, Wsig, bsig, out);
}